// round 15
// baseline (speedup 1.0000x reference)
#include <cuda_runtime.h>
#include <cuda_bf16.h>
#include <cstdint>

#define U_N 100000
#define I_N 50000
#define N_TOT (U_N + I_N)
#define HD  128
#define HD2 64                 // packed b32 (bf16x2) per row
#define E_N 600000
#define EL_N 200000

#define NPAD 150528            // 147 * 1024  >= U_N + I_N + 1
#define NBLK 147

// ---------------- scratch (device globals: allocation-free) ----------------
// cnt/desc are zero at module load and re-zeroed by cleanup_kernel at the END
// of every kernel_launch call -> state at entry is identical each call.
__device__ float    g_u1[(size_t)U_N * HD];
__device__ float    g_i1[(size_t)I_N * HD];
__device__ float    g_u2[(size_t)U_N * HD];
__device__ float    g_i2[(size_t)I_N * HD];
__device__ uint32_t g_mean_hi[(size_t)N_TOT * HD2];
__device__ uint32_t g_mean_lo[(size_t)N_TOT * HD2];
__device__ uint32_t g_x1_hi[(size_t)N_TOT * HD2];   // layer-1 x side (packed emb)
__device__ uint32_t g_x1_lo[(size_t)N_TOT * HD2];
__device__ uint32_t g_x2_hi[(size_t)N_TOT * HD2];   // layer-2 x side (packed u1/i1)
__device__ uint32_t g_x2_lo[(size_t)N_TOT * HD2];
__device__ uint32_t g_wpk[8 * 2 * 64 * 128];        // 8 weights x {hi,lo}[64][128]
__device__ int      g_cnt[NPAD];
__device__ int      g_off[NPAD + 1];
__device__ int      g_cur[NPAD];
__device__ unsigned long long g_desc[NBLK];
__device__ int      g_esrc_u[E_N];
__device__ int      g_esrc_i[E_N];

#define ST_AGG (1ull << 62)
#define ST_PRE (2ull << 62)

// ---------------- helpers ----------------------------------------------------
__device__ __forceinline__ float bfr(float x) {
    return __bfloat162float(__float2bfloat16_rn(x));
}
__device__ __forceinline__ uint32_t pkbf(float lo, float hi) {
    __nv_bfloat162 t = __floats2bfloat162_rn(lo, hi);   // (lo, hi)
    return *reinterpret_cast<uint32_t*>(&t);
}
__device__ __forceinline__ void mma_bf16(float c[4], const uint32_t a[4],
                                         const uint32_t b[2]) {
    asm volatile(
        "mma.sync.aligned.m16n8k16.row.col.f32.bf16.bf16.f32 "
        "{%0,%1,%2,%3}, {%4,%5,%6,%7}, {%8,%9}, {%0,%1,%2,%3};"
        : "+f"(c[0]), "+f"(c[1]), "+f"(c[2]), "+f"(c[3])
        : "r"(a[0]), "r"(a[1]), "r"(a[2]), "r"(a[3]), "r"(b[0]), "r"(b[1]));
}

// ---------------- CSR build (3 launches) ------------------------------------
__global__ void hist_kernel(const int* __restrict__ ei, int* __restrict__ cnt) {
    int e = blockIdx.x * blockDim.x + threadIdx.x;
    if (e >= E_N) return;
    atomicAdd(cnt + ei[e], 1);
    atomicAdd(cnt + U_N + ei[E_N + e], 1);
}

__global__ void scan_lookback(const int* __restrict__ cnt, int* __restrict__ off,
                              int* __restrict__ cur,
                              unsigned long long* __restrict__ desc) {
    __shared__ int ws[32];
    __shared__ int s_prefix;
    const int b = blockIdx.x;
    const int i = b * 1024 + threadIdx.x;
    const int lane = threadIdx.x & 31, wid = threadIdx.x >> 5;
    int v = cnt[i];
    int x = v;
#pragma unroll
    for (int o = 1; o < 32; o <<= 1) {
        int t = __shfl_up_sync(0xFFFFFFFFu, x, o);
        if (lane >= o) x += t;
    }
    if (lane == 31) ws[wid] = x;
    __syncthreads();
    if (wid == 0) {
        int s = ws[lane];
#pragma unroll
        for (int o = 1; o < 32; o <<= 1) {
            int t = __shfl_up_sync(0xFFFFFFFFu, s, o);
            if (lane >= o) s += t;
        }
        ws[lane] = s;
    }
    __syncthreads();
    const int total = ws[31];
    const int wpre = (wid > 0) ? ws[wid - 1] : 0;
    const int excl = wpre + x - v;

    if (threadIdx.x == 0) {
        unsigned long long d = ((b == 0) ? ST_PRE : ST_AGG) | (unsigned)total;
        atomicExch(&desc[b], d);
    }

    if (wid == 0) {
        int prefix = 0;
        if (b > 0) {
            int end = b;
            while (true) {
                int idx = end - 1 - lane;
                unsigned long long e = (idx >= 0) ? atomicAdd(&desc[idx], 0ull)
                                                  : ST_PRE;
                unsigned st = (unsigned)(e >> 62);
                int val = (int)(unsigned)e;
                unsigned pre_mask = __ballot_sync(0xFFFFFFFFu, st == 2u);
                unsigned inv_mask = __ballot_sync(0xFFFFFFFFu, st == 0u);
                if (pre_mask) {
                    int L = __ffs(pre_mask) - 1;
                    if ((inv_mask & ((1u << L) - 1u)) == 0u) {
                        int contrib = (lane <= L) ? val : 0;
#pragma unroll
                        for (int o = 16; o > 0; o >>= 1)
                            contrib += __shfl_xor_sync(0xFFFFFFFFu, contrib, o);
                        prefix += contrib;
                        break;
                    }
                } else if (inv_mask == 0u) {
                    int contrib = val;
#pragma unroll
                    for (int o = 16; o > 0; o >>= 1)
                        contrib += __shfl_xor_sync(0xFFFFFFFFu, contrib, o);
                    prefix += contrib;
                    end -= 32;
                }
            }
            if (lane == 0)
                atomicExch(&desc[b], ST_PRE | (unsigned)(prefix + total));
        }
        if (lane == 0) s_prefix = prefix;
    }
    __syncthreads();
    int o = s_prefix + excl;
    off[i] = o;
    cur[i] = o;
    if (i == NPAD - 1) off[NPAD] = o + v;
}

__global__ void place_kernel(const int* __restrict__ ei, int* __restrict__ cur,
                             int* __restrict__ esrc_u, int* __restrict__ esrc_i) {
    int e = blockIdx.x * blockDim.x + threadIdx.x;
    if (e >= E_N) return;
    int u  = ei[e];
    int it = ei[E_N + e];
    int p = atomicAdd(cur + u, 1);
    esrc_u[p] = it;
    int q = atomicAdd(cur + U_N + it, 1) - E_N;
    esrc_i[q] = u;
}

// ---------------- CSR mean gather -> packed bf16 hi/lo ----------------------
__global__ void mean_all(const int* __restrict__ off,
                         const int* __restrict__ esrc_u, const int* __restrict__ esrc_i,
                         const float* __restrict__ xs_u, const float* __restrict__ xs_i,
                         uint32_t* __restrict__ mhi, uint32_t* __restrict__ mlo) {
    int node = blockIdx.x * 8 + (threadIdx.x >> 5);
    if (node >= N_TOT) return;
    int lane = threadIdx.x & 31;
    const bool isU = node < U_N;
    const float* __restrict__ x_src = isU ? xs_u : xs_i;
    const int* __restrict__ esrc = isU ? esrc_u : esrc_i;
    int o0 = off[node];
    int deg = off[node + 1] - o0;
    int estart = isU ? o0 : (o0 - E_N);

    float4 acc = make_float4(0.f, 0.f, 0.f, 0.f);
#pragma unroll 1
    for (int j = 0; j < deg; j += 32) {
        int sid = (j + lane < deg) ? esrc[estart + j + lane] : 0;
        int lim = min(32, deg - j);
        float4 b0, b1, b2, b3;
        int s;
        s = __shfl_sync(0xFFFFFFFFu, sid, 0);
        b0 = ((const float4*)(x_src + (size_t)s * HD))[lane];
        if (1 < lim) { s = __shfl_sync(0xFFFFFFFFu, sid, 1);
                       b1 = ((const float4*)(x_src + (size_t)s * HD))[lane]; }
        if (2 < lim) { s = __shfl_sync(0xFFFFFFFFu, sid, 2);
                       b2 = ((const float4*)(x_src + (size_t)s * HD))[lane]; }
        if (3 < lim) { s = __shfl_sync(0xFFFFFFFFu, sid, 3);
                       b3 = ((const float4*)(x_src + (size_t)s * HD))[lane]; }
#pragma unroll 1
        for (int jj = 0; jj < lim; jj += 4) {
            acc.x += b0.x; acc.y += b0.y; acc.z += b0.z; acc.w += b0.w;
            if (jj + 4 < lim) {
                s = __shfl_sync(0xFFFFFFFFu, sid, jj + 4);
                b0 = ((const float4*)(x_src + (size_t)s * HD))[lane];
            }
            if (jj + 1 < lim) {
                acc.x += b1.x; acc.y += b1.y; acc.z += b1.z; acc.w += b1.w;
                if (jj + 5 < lim) {
                    s = __shfl_sync(0xFFFFFFFFu, sid, jj + 5);
                    b1 = ((const float4*)(x_src + (size_t)s * HD))[lane];
                }
            }
            if (jj + 2 < lim) {
                acc.x += b2.x; acc.y += b2.y; acc.z += b2.z; acc.w += b2.w;
                if (jj + 6 < lim) {
                    s = __shfl_sync(0xFFFFFFFFu, sid, jj + 6);
                    b2 = ((const float4*)(x_src + (size_t)s * HD))[lane];
                }
            }
            if (jj + 3 < lim) {
                acc.x += b3.x; acc.y += b3.y; acc.z += b3.z; acc.w += b3.w;
                if (jj + 7 < lim) {
                    s = __shfl_sync(0xFFFFFFFFu, sid, jj + 7);
                    b3 = ((const float4*)(x_src + (size_t)s * HD))[lane];
                }
            }
        }
    }
    float sc = 1.0f / fmaxf((float)deg, 1.0f);
    float4 m = make_float4(acc.x * sc, acc.y * sc, acc.z * sc, acc.w * sc);
    // pack: lane owns k = lane*4..lane*4+3 -> kk2 = lane*2, lane*2+1
    float hx = bfr(m.x), hy = bfr(m.y), hz = bfr(m.z), hw = bfr(m.w);
    uint2 hv = make_uint2(pkbf(hx, hy), pkbf(hz, hw));
    uint2 lv = make_uint2(pkbf(m.x - hx, m.y - hy), pkbf(m.z - hz, m.w - hw));
    ((uint2*)(mhi + (size_t)node * HD2))[lane] = hv;
    ((uint2*)(mlo + (size_t)node * HD2))[lane] = lv;
}

// ---------------- weight pre-pack: [kk2][n] bf16x2 hi/lo --------------------
__global__ void wpack_kernel(const float* w0, const float* w1, const float* w2,
                             const float* w3, const float* w4, const float* w5,
                             const float* w6, const float* w7,
                             uint32_t* __restrict__ wpk) {
    const float* ws[8] = {w0, w1, w2, w3, w4, w5, w6, w7};
    const float* __restrict__ W = ws[blockIdx.x];
    uint32_t* base = wpk + blockIdx.x * 16384;
    int n = threadIdx.x;                       // 0..127
#pragma unroll 1
    for (int kk2 = 0; kk2 < 64; kk2++) {
        float a = W[(2 * kk2) * 128 + n];
        float b = W[(2 * kk2 + 1) * 128 + n];
        float ha = bfr(a), hb = bfr(b);
        base[kk2 * 128 + n] = pkbf(ha, hb);
        base[8192 + kk2 * 128 + n] = pkbf(a - ha, b - hb);
    }
}

// ---------------- embedding pre-pack: row-major [node][kk2] hi/lo -----------
__global__ void epack_kernel(const float* __restrict__ xu, const float* __restrict__ xi,
                             uint32_t* __restrict__ xhi, uint32_t* __restrict__ xlo) {
    int row = blockIdx.x * 8 + (threadIdx.x >> 5);
    if (row >= N_TOT) return;
    int lane = threadIdx.x & 31;
    const float* src = (row < U_N) ? (xu + (size_t)row * HD)
                                   : (xi + (size_t)(row - U_N) * HD);
    float4 v = ((const float4*)src)[lane];
    float hx = bfr(v.x), hy = bfr(v.y), hz = bfr(v.z), hw = bfr(v.w);
    uint2 hv = make_uint2(pkbf(hx, hy), pkbf(hz, hw));
    uint2 lv = make_uint2(pkbf(v.x - hx, v.y - hy), pkbf(v.z - hz, v.w - hw));
    ((uint2*)(xhi + (size_t)row * HD2))[lane] = hv;
    ((uint2*)(xlo + (size_t)row * HD2))[lane] = lv;
}

// ---------------- bf16-split mma.sync SAGE GEMM (pre-packed operands) -------
// A = [mean | x] packed hi/lo bf16x2, W pre-packed. No cvt in the mainloop.
// RELU=true (layer 1) also emits packed hi/lo of the output for gemm2's x side.
#define PITCH 136
#define SM_CH (16 * PITCH)
#define GEMM_SMEM (4 * SM_CH * 4)
#define UBK ((U_N + 127) / 128)
#define IBK ((I_N + 127) / 128)

template <bool RELU>
__global__ __launch_bounds__(256, 2)
void sage_gemm_mma(const uint32_t* __restrict__ mhi, const uint32_t* __restrict__ mlo,
                   const uint32_t* __restrict__ xhi, const uint32_t* __restrict__ xlo,
                   const uint32_t* __restrict__ wpk_u,   // hi at +0, lo at +8192; Wl at +0, Wr at +16384
                   const uint32_t* __restrict__ wpk_i,
                   const float* __restrict__ bias_u, const float* __restrict__ bias_i,
                   float* __restrict__ out_u, float* __restrict__ out_i,
                   uint32_t* __restrict__ oxhi, uint32_t* __restrict__ oxlo) {
    extern __shared__ uint32_t sm[];
    uint32_t* Ash = sm;
    uint32_t* Asl = sm + SM_CH;
    uint32_t* Bsh = sm + 2 * SM_CH;
    uint32_t* Bsl = sm + 3 * SM_CH;

    const bool isU = blockIdx.x < UBK;
    const int bid = isU ? blockIdx.x : (blockIdx.x - UBK);
    const int M = isU ? U_N : I_N;
    const size_t nbase = isU ? 0 : (size_t)U_N;
    const uint32_t* __restrict__ wpk = isU ? wpk_u : wpk_i;
    const float* __restrict__ bias = isU ? bias_u : bias_i;
    float* __restrict__ out = isU ? out_u : out_i;

    const int tid = threadIdx.x;
    const int lane = tid & 31;
    const int wid = tid >> 5;
    const int wm = wid & 3;
    const int wn = wid >> 2;
    const int row0 = bid * 128;
    const int g = lane >> 2;
    const int tig = lane & 3;

    float c[2][8][4];
#pragma unroll
    for (int mt = 0; mt < 2; mt++)
#pragma unroll
        for (int nt = 0; nt < 8; nt++)
#pragma unroll
            for (int q = 0; q < 4; q++) c[mt][nt][q] = 0.f;

#pragma unroll 1
    for (int kt = 0; kt < 8; kt++) {
        const bool isAgg = kt < 4;
        const int kk2base = (kt & 3) * 16;
        const uint32_t* __restrict__ AH = isAgg ? mhi : xhi;
        const uint32_t* __restrict__ AL = isAgg ? mlo : xlo;
        const uint32_t* __restrict__ WB = wpk + (isAgg ? 0 : 16384);

        // A chunk: per row 16 kk2 hi (4 uint4) + 16 lo; 1024 uint4 over 4 reps
#pragma unroll
        for (int rep = 0; rep < 4; rep++) {
            int fid = tid + rep * 256;
            int r = fid >> 3;              // 0..127
            int q = fid & 7;               // 0..7; q<4 hi, q>=4 lo
            int q4 = q & 3;
            int grow = row0 + r;
            uint4 v = make_uint4(0u, 0u, 0u, 0u);
            const uint32_t* src = (q < 4) ? AH : AL;
            if (grow < M)
                v = *(const uint4*)(src + (nbase + grow) * HD2 + kk2base + q4 * 4);
            uint32_t* dst = (q < 4) ? Ash : Asl;
            dst[(q4 * 4 + 0) * PITCH + r] = v.x;
            dst[(q4 * 4 + 1) * PITCH + r] = v.y;
            dst[(q4 * 4 + 2) * PITCH + r] = v.z;
            dst[(q4 * 4 + 3) * PITCH + r] = v.w;
        }
        // B chunk: [16][128] b32 hi + lo = 1024 uint4 over 4 reps
#pragma unroll
        for (int rep = 0; rep < 4; rep++) {
            int fid = tid + rep * 256;
            bool isLo = fid >= 512;
            int f = fid & 511;
            int kk2 = f >> 5;              // 0..15
            int n4 = f & 31;               // 0..31
            const uint32_t* src = WB + (isLo ? 8192 : 0) + (kk2base + kk2) * 128;
            uint4 v = ((const uint4*)src)[n4];
            *(uint4*)&(isLo ? Bsl : Bsh)[kk2 * PITCH + n4 * 4] = v;
        }
        __syncthreads();

#pragma unroll
        for (int ks = 0; ks < 2; ks++) {
            const int arow = ks * 8;
            uint32_t ah[2][4], al[2][4];
#pragma unroll
            for (int mt = 0; mt < 2; mt++) {
                int m0 = wm * 32 + mt * 16;
                ah[mt][0] = Ash[(arow + tig) * PITCH + m0 + g];
                ah[mt][1] = Ash[(arow + tig) * PITCH + m0 + g + 8];
                ah[mt][2] = Ash[(arow + tig + 4) * PITCH + m0 + g];
                ah[mt][3] = Ash[(arow + tig + 4) * PITCH + m0 + g + 8];
                al[mt][0] = Asl[(arow + tig) * PITCH + m0 + g];
                al[mt][1] = Asl[(arow + tig) * PITCH + m0 + g + 8];
                al[mt][2] = Asl[(arow + tig + 4) * PITCH + m0 + g];
                al[mt][3] = Asl[(arow + tig + 4) * PITCH + m0 + g + 8];
            }
#pragma unroll
            for (int nt = 0; nt < 8; nt++) {
                int n0 = wn * 64 + nt * 8;
                uint32_t bh[2], bl[2];
                bh[0] = Bsh[(arow + tig) * PITCH + n0 + g];
                bh[1] = Bsh[(arow + tig + 4) * PITCH + n0 + g];
                bl[0] = Bsl[(arow + tig) * PITCH + n0 + g];
                bl[1] = Bsl[(arow + tig + 4) * PITCH + n0 + g];
                mma_bf16(c[0][nt], ah[0], bh);
                mma_bf16(c[1][nt], ah[1], bh);
                mma_bf16(c[0][nt], ah[0], bl);
                mma_bf16(c[1][nt], ah[1], bl);
                mma_bf16(c[0][nt], al[0], bh);
                mma_bf16(c[1][nt], al[1], bh);
            }
        }
        __syncthreads();
    }

    // epilogue: fp32 store; layer-1 also stores packed hi/lo for gemm2 x side
#pragma unroll
    for (int mt = 0; mt < 2; mt++) {
        int r_lo = row0 + wm * 32 + mt * 16 + g;
        int r_hi = r_lo + 8;
#pragma unroll
        for (int nt = 0; nt < 8; nt++) {
            int col = wn * 64 + nt * 8 + tig * 2;
            int kk2 = col >> 1;
            float b0 = bias[col], b1 = bias[col + 1];
            float v0 = c[mt][nt][0] + b0;
            float v1 = c[mt][nt][1] + b1;
            float v2 = c[mt][nt][2] + b0;
            float v3 = c[mt][nt][3] + b1;
            if (RELU) {
                v0 = fmaxf(v0, 0.f); v1 = fmaxf(v1, 0.f);
                v2 = fmaxf(v2, 0.f); v3 = fmaxf(v3, 0.f);
            }
            if (r_lo < M) {
                *(float2*)(out + (size_t)r_lo * HD + col) = make_float2(v0, v1);
                if (RELU) {
                    float h0 = bfr(v0), h1 = bfr(v1);
                    oxhi[(nbase + r_lo) * HD2 + kk2] = pkbf(h0, h1);
                    oxlo[(nbase + r_lo) * HD2 + kk2] = pkbf(v0 - h0, v1 - h1);
                }
            }
            if (r_hi < M) {
                *(float2*)(out + (size_t)r_hi * HD + col) = make_float2(v2, v3);
                if (RELU) {
                    float h2 = bfr(v2), h3 = bfr(v3);
                    oxhi[(nbase + r_hi) * HD2 + kk2] = pkbf(h2, h3);
                    oxlo[(nbase + r_hi) * HD2 + kk2] = pkbf(v2 - h2, v3 - h3);
                }
            }
        }
    }
}

// ---------------- edge dot-product classifier ------------------------------
__global__ void classify_kernel(const float* __restrict__ u2, const float* __restrict__ i2,
                                const int* __restrict__ lbl, float* __restrict__ out) {
    int e = blockIdx.x * (blockDim.x >> 5) + (threadIdx.x >> 5);
    if (e >= EL_N) return;
    int lane = threadIdx.x & 31;
    int u  = lbl[e];
    int it = lbl[EL_N + e];
    float4 a = ((const float4*)(u2 + (size_t)u * HD))[lane];
    float4 b = ((const float4*)(i2 + (size_t)it * HD))[lane];
    float s = a.x * b.x + a.y * b.y + a.z * b.z + a.w * b.w;
#pragma unroll
    for (int o = 16; o > 0; o >>= 1) s += __shfl_xor_sync(0xFFFFFFFFu, s, o);
    if (lane == 0) out[e] = s;
}

// ---------------- cleanup: restore zero-state for next call -----------------
__global__ void cleanup_kernel(int* __restrict__ cnt,
                               unsigned long long* __restrict__ desc) {
    int i = blockIdx.x * blockDim.x + threadIdx.x;
    if (i < NPAD) cnt[i] = 0;
    if (i < NBLK) desc[i] = 0ull;
}

// ---------------- launch ----------------------------------------------------
extern "C" void kernel_launch(void* const* d_in, const int* in_sizes, int n_in,
                              void* d_out, int out_size) {
    const float* user_emb = (const float*)d_in[0];
    const float* item_emb = (const float*)d_in[1];
    const float* w1_ui_l = (const float*)d_in[2];
    const float* w1_ui_r = (const float*)d_in[3];
    const float* w1_iu_l = (const float*)d_in[4];
    const float* w1_iu_r = (const float*)d_in[5];
    const float* w2_ui_l = (const float*)d_in[6];
    const float* w2_ui_r = (const float*)d_in[7];
    const float* w2_iu_l = (const float*)d_in[8];
    const float* w2_iu_r = (const float*)d_in[9];
    const float* b1_ui = (const float*)d_in[10];
    const float* b1_iu = (const float*)d_in[11];
    const float* b2_ui = (const float*)d_in[12];
    const float* b2_iu = (const float*)d_in[13];
    const int* ei_ui = (const int*)d_in[16];
    const int* lbl   = (const int*)d_in[18];
    float* out = (float*)d_out;

    float *u1, *i1, *u2, *i2;
    uint32_t *mhi, *mlo, *x1h, *x1l, *x2h, *x2l, *wpk;
    int *cnt, *cur, *off, *esrc_u, *esrc_i;
    unsigned long long* desc;
    cudaGetSymbolAddress((void**)&u1, g_u1);
    cudaGetSymbolAddress((void**)&i1, g_i1);
    cudaGetSymbolAddress((void**)&u2, g_u2);
    cudaGetSymbolAddress((void**)&i2, g_i2);
    cudaGetSymbolAddress((void**)&mhi, g_mean_hi);
    cudaGetSymbolAddress((void**)&mlo, g_mean_lo);
    cudaGetSymbolAddress((void**)&x1h, g_x1_hi);
    cudaGetSymbolAddress((void**)&x1l, g_x1_lo);
    cudaGetSymbolAddress((void**)&x2h, g_x2_hi);
    cudaGetSymbolAddress((void**)&x2l, g_x2_lo);
    cudaGetSymbolAddress((void**)&wpk, g_wpk);
    cudaGetSymbolAddress((void**)&cnt, g_cnt);
    cudaGetSymbolAddress((void**)&cur, g_cur);
    cudaGetSymbolAddress((void**)&off, g_off);
    cudaGetSymbolAddress((void**)&desc, g_desc);
    cudaGetSymbolAddress((void**)&esrc_u, g_esrc_u);
    cudaGetSymbolAddress((void**)&esrc_i, g_esrc_i);

    cudaFuncSetAttribute(sage_gemm_mma<true>,
                         cudaFuncAttributeMaxDynamicSharedMemorySize, GEMM_SMEM);
    cudaFuncSetAttribute(sage_gemm_mma<false>,
                         cudaFuncAttributeMaxDynamicSharedMemorySize, GEMM_SMEM);

    // ---- CSR build: 3 launches (cnt/desc pre-zeroed by prior cleanup) ----
    hist_kernel<<<(E_N + 255) / 256, 256>>>(ei_ui, cnt);            // 0
    scan_lookback<<<NBLK, 1024>>>(cnt, off, cur, desc);             // 1
    place_kernel<<<(E_N + 255) / 256, 256>>>(ei_ui, cur,
                                             esrc_u, esrc_i);       // 2

    const int MB = (N_TOT + 7) / 8;

    // ---- layer 1 ----
    mean_all<<<MB, 256>>>(off, esrc_u, esrc_i,
                          item_emb, user_emb, mhi, mlo);            // 3 (profiled)
    // weight order: 0=w1_iu_l 1=w1_iu_r 2=w1_ui_l 3=w1_ui_r 4..7=layer2
    wpack_kernel<<<8, 128>>>(w1_iu_l, w1_iu_r, w1_ui_l, w1_ui_r,
                             w2_iu_l, w2_iu_r, w2_ui_l, w2_ui_r, wpk); // 4
    epack_kernel<<<MB, 256>>>(user_emb, item_emb, x1h, x1l);        // 5
    sage_gemm_mma<true><<<UBK + IBK, 256, GEMM_SMEM>>>(
        mhi, mlo, x1h, x1l,
        wpk + 0 * 16384 /* u: Wl=w1_iu_l, Wr at +16384 = w1_iu_r */,
        wpk + 2 * 16384 /* i: Wl=w1_ui_l, Wr=w1_ui_r */,
        b1_iu, b1_ui, u1, i1, x2h, x2l);                            // 6

    // ---- layer 2 ----
    mean_all<<<MB, 256>>>(off, esrc_u, esrc_i, i1, u1, mhi, mlo);   // 7
    sage_gemm_mma<false><<<UBK + IBK, 256, GEMM_SMEM>>>(
        mhi, mlo, x2h, x2l,
        wpk + 4 * 16384, wpk + 6 * 16384,
        b2_iu, b2_ui, u2, i2, (uint32_t*)nullptr, (uint32_t*)nullptr); // 8

    // ---- classifier ----
    classify_kernel<<<(EL_N + 7) / 8, 256>>>(u2, i2, lbl, out);     // 9

    // ---- restore zero-state for next call ----
    cleanup_kernel<<<(NPAD + 1023) / 1024, 1024>>>(cnt, desc);      // 10
}

// round 16
// speedup vs baseline: 1.2246x; 1.2246x over previous
#include <cuda_runtime.h>
#include <cuda_bf16.h>
#include <cstdint>

#define U_N 100000
#define I_N 50000
#define N_TOT (U_N + I_N)
#define HD  128
#define E_N 600000
#define EL_N 200000

#define NPAD 150528            // 147 * 1024  >= U_N + I_N + 1
#define NBLK 147

// ---------------- scratch (device globals: allocation-free) ----------------
// cnt/desc are zero at module load and re-zeroed by cleanup_kernel at the END
// of every kernel_launch call -> state at entry is identical each call.
__device__ float    g_u1[(size_t)U_N * HD];
__device__ float    g_i1[(size_t)I_N * HD];
__device__ float    g_u2[(size_t)U_N * HD];
__device__ float    g_i2[(size_t)I_N * HD];
__device__ float    g_mean[(size_t)N_TOT * HD];
__device__ uint32_t g_wpk[8 * 2 * 64 * 128];   // 8 weights x {hi,lo}[64 kk2][128 n]
__device__ int      g_cnt[NPAD];
__device__ int      g_off[NPAD + 1];
__device__ int      g_cur[NPAD];
__device__ unsigned long long g_desc[NBLK];
__device__ int      g_esrc_u[E_N];
__device__ int      g_esrc_i[E_N];

#define ST_AGG (1ull << 62)
#define ST_PRE (2ull << 62)

// ---------------- helpers ----------------------------------------------------
__device__ __forceinline__ float bfr(float x) {
    return __bfloat162float(__float2bfloat16_rn(x));
}
__device__ __forceinline__ uint32_t pkbf(float lo, float hi) {
    __nv_bfloat162 t = __floats2bfloat162_rn(lo, hi);   // (lo, hi)
    return *reinterpret_cast<uint32_t*>(&t);
}
__device__ __forceinline__ void mma_bf16(float c[4], const uint32_t a[4],
                                         const uint32_t b[2]) {
    asm volatile(
        "mma.sync.aligned.m16n8k16.row.col.f32.bf16.bf16.f32 "
        "{%0,%1,%2,%3}, {%4,%5,%6,%7}, {%8,%9}, {%0,%1,%2,%3};"
        : "+f"(c[0]), "+f"(c[1]), "+f"(c[2]), "+f"(c[3])
        : "r"(a[0]), "r"(a[1]), "r"(a[2]), "r"(a[3]), "r"(b[0]), "r"(b[1]));
}

// ---------------- CSR build (3 launches) ------------------------------------
__global__ void hist_kernel(const int* __restrict__ ei, int* __restrict__ cnt) {
    int e = blockIdx.x * blockDim.x + threadIdx.x;
    if (e >= E_N) return;
    atomicAdd(cnt + ei[e], 1);
    atomicAdd(cnt + U_N + ei[E_N + e], 1);
}

__global__ void scan_lookback(const int* __restrict__ cnt, int* __restrict__ off,
                              int* __restrict__ cur,
                              unsigned long long* __restrict__ desc) {
    __shared__ int ws[32];
    __shared__ int s_prefix;
    const int b = blockIdx.x;
    const int i = b * 1024 + threadIdx.x;
    const int lane = threadIdx.x & 31, wid = threadIdx.x >> 5;
    int v = cnt[i];
    int x = v;
#pragma unroll
    for (int o = 1; o < 32; o <<= 1) {
        int t = __shfl_up_sync(0xFFFFFFFFu, x, o);
        if (lane >= o) x += t;
    }
    if (lane == 31) ws[wid] = x;
    __syncthreads();
    if (wid == 0) {
        int s = ws[lane];
#pragma unroll
        for (int o = 1; o < 32; o <<= 1) {
            int t = __shfl_up_sync(0xFFFFFFFFu, s, o);
            if (lane >= o) s += t;
        }
        ws[lane] = s;
    }
    __syncthreads();
    const int total = ws[31];
    const int wpre = (wid > 0) ? ws[wid - 1] : 0;
    const int excl = wpre + x - v;

    if (threadIdx.x == 0) {
        unsigned long long d = ((b == 0) ? ST_PRE : ST_AGG) | (unsigned)total;
        atomicExch(&desc[b], d);
    }

    if (wid == 0) {
        int prefix = 0;
        if (b > 0) {
            int end = b;
            while (true) {
                int idx = end - 1 - lane;
                unsigned long long e = (idx >= 0) ? atomicAdd(&desc[idx], 0ull)
                                                  : ST_PRE;
                unsigned st = (unsigned)(e >> 62);
                int val = (int)(unsigned)e;
                unsigned pre_mask = __ballot_sync(0xFFFFFFFFu, st == 2u);
                unsigned inv_mask = __ballot_sync(0xFFFFFFFFu, st == 0u);
                if (pre_mask) {
                    int L = __ffs(pre_mask) - 1;
                    if ((inv_mask & ((1u << L) - 1u)) == 0u) {
                        int contrib = (lane <= L) ? val : 0;
#pragma unroll
                        for (int o = 16; o > 0; o >>= 1)
                            contrib += __shfl_xor_sync(0xFFFFFFFFu, contrib, o);
                        prefix += contrib;
                        break;
                    }
                } else if (inv_mask == 0u) {
                    int contrib = val;
#pragma unroll
                    for (int o = 16; o > 0; o >>= 1)
                        contrib += __shfl_xor_sync(0xFFFFFFFFu, contrib, o);
                    prefix += contrib;
                    end -= 32;
                }
            }
            if (lane == 0)
                atomicExch(&desc[b], ST_PRE | (unsigned)(prefix + total));
        }
        if (lane == 0) s_prefix = prefix;
    }
    __syncthreads();
    int o = s_prefix + excl;
    off[i] = o;
    cur[i] = o;
    if (i == NPAD - 1) off[NPAD] = o + v;
}

__global__ void place_kernel(const int* __restrict__ ei, int* __restrict__ cur,
                             int* __restrict__ esrc_u, int* __restrict__ esrc_i) {
    int e = blockIdx.x * blockDim.x + threadIdx.x;
    if (e >= E_N) return;
    int u  = ei[e];
    int it = ei[E_N + e];
    int p = atomicAdd(cur + u, 1);
    esrc_u[p] = it;
    int q = atomicAdd(cur + U_N + it, 1) - E_N;
    esrc_i[q] = u;
}

// ---------------- merged CSR mean gather (warp/node, depth-4 pipeline) ------
__global__ void mean_all(const int* __restrict__ off,
                         const int* __restrict__ esrc_u, const int* __restrict__ esrc_i,
                         const float* __restrict__ xs_u, const float* __restrict__ xs_i,
                         float* __restrict__ mean_out) {
    int node = blockIdx.x * 8 + (threadIdx.x >> 5);
    if (node >= N_TOT) return;
    int lane = threadIdx.x & 31;
    const bool isU = node < U_N;
    const float* __restrict__ x_src = isU ? xs_u : xs_i;
    const int* __restrict__ esrc = isU ? esrc_u : esrc_i;
    int o0 = off[node];
    int deg = off[node + 1] - o0;
    int estart = isU ? o0 : (o0 - E_N);

    float4 acc = make_float4(0.f, 0.f, 0.f, 0.f);
#pragma unroll 1
    for (int j = 0; j < deg; j += 32) {
        int sid = (j + lane < deg) ? esrc[estart + j + lane] : 0;
        int lim = min(32, deg - j);
        float4 b0, b1, b2, b3;
        int s;
        s = __shfl_sync(0xFFFFFFFFu, sid, 0);
        b0 = ((const float4*)(x_src + (size_t)s * HD))[lane];
        if (1 < lim) { s = __shfl_sync(0xFFFFFFFFu, sid, 1);
                       b1 = ((const float4*)(x_src + (size_t)s * HD))[lane]; }
        if (2 < lim) { s = __shfl_sync(0xFFFFFFFFu, sid, 2);
                       b2 = ((const float4*)(x_src + (size_t)s * HD))[lane]; }
        if (3 < lim) { s = __shfl_sync(0xFFFFFFFFu, sid, 3);
                       b3 = ((const float4*)(x_src + (size_t)s * HD))[lane]; }
#pragma unroll 1
        for (int jj = 0; jj < lim; jj += 4) {
            acc.x += b0.x; acc.y += b0.y; acc.z += b0.z; acc.w += b0.w;
            if (jj + 4 < lim) {
                s = __shfl_sync(0xFFFFFFFFu, sid, jj + 4);
                b0 = ((const float4*)(x_src + (size_t)s * HD))[lane];
            }
            if (jj + 1 < lim) {
                acc.x += b1.x; acc.y += b1.y; acc.z += b1.z; acc.w += b1.w;
                if (jj + 5 < lim) {
                    s = __shfl_sync(0xFFFFFFFFu, sid, jj + 5);
                    b1 = ((const float4*)(x_src + (size_t)s * HD))[lane];
                }
            }
            if (jj + 2 < lim) {
                acc.x += b2.x; acc.y += b2.y; acc.z += b2.z; acc.w += b2.w;
                if (jj + 6 < lim) {
                    s = __shfl_sync(0xFFFFFFFFu, sid, jj + 6);
                    b2 = ((const float4*)(x_src + (size_t)s * HD))[lane];
                }
            }
            if (jj + 3 < lim) {
                acc.x += b3.x; acc.y += b3.y; acc.z += b3.z; acc.w += b3.w;
                if (jj + 7 < lim) {
                    s = __shfl_sync(0xFFFFFFFFu, sid, jj + 7);
                    b3 = ((const float4*)(x_src + (size_t)s * HD))[lane];
                }
            }
        }
    }
    float sc = 1.0f / fmaxf((float)deg, 1.0f);
    float4 m = make_float4(acc.x * sc, acc.y * sc, acc.z * sc, acc.w * sc);
    ((float4*)(mean_out + (size_t)node * HD))[lane] = m;
}

// ---------------- weight pre-pack: [kk2][n] bf16x2 hi/lo --------------------
__global__ void wpack_kernel(const float* w0, const float* w1, const float* w2,
                             const float* w3, const float* w4, const float* w5,
                             const float* w6, const float* w7,
                             uint32_t* __restrict__ wpk) {
    const float* ws[8] = {w0, w1, w2, w3, w4, w5, w6, w7};
    const float* __restrict__ W = ws[blockIdx.x];
    uint32_t* base = wpk + blockIdx.x * 16384;
    int n = threadIdx.x;                       // 0..127
#pragma unroll 1
    for (int kk2 = 0; kk2 < 64; kk2++) {
        float a = W[(2 * kk2) * 128 + n];
        float b = W[(2 * kk2 + 1) * 128 + n];
        float ha = bfr(a), hb = bfr(b);
        base[kk2 * 128 + n] = pkbf(ha, hb);
        base[8192 + kk2 * 128 + n] = pkbf(a - ha, b - hb);
    }
}

// ---------------- merged 3x bf16-split mma.sync SAGE GEMM -------------------
// Identical to the 418us r13 kernel EXCEPT the B-tile fill, which now loads
// pre-packed bf16x2 hi/lo from wpk (same smem layout/addresses, no cvt).
#define PITCH 136
#define SM_CH (16 * PITCH)               // b32 elements per frag array
#define GEMM_SMEM (4 * SM_CH * 4)
#define UBK ((U_N + 127) / 128)
#define IBK ((I_N + 127) / 128)

template <bool RELU>
__global__ __launch_bounds__(256, 2)
void sage_gemm_mma(const float* __restrict__ mean_all_buf,
                   const float* __restrict__ xd_u, const float* __restrict__ xd_i,
                   const uint32_t* __restrict__ wpk_u,  // Wl hi@0 lo@8192; Wr @+16384
                   const uint32_t* __restrict__ wpk_i,
                   const float* __restrict__ bias_u, const float* __restrict__ bias_i,
                   float* __restrict__ out_u, float* __restrict__ out_i) {
    extern __shared__ uint32_t sm[];
    uint32_t* Ash = sm;
    uint32_t* Asl = sm + SM_CH;
    uint32_t* Bsh = sm + 2 * SM_CH;
    uint32_t* Bsl = sm + 3 * SM_CH;

    const bool isU = blockIdx.x < UBK;
    const int bid = isU ? blockIdx.x : (blockIdx.x - UBK);
    const int M = isU ? U_N : I_N;
    const float* __restrict__ meanA = mean_all_buf + (isU ? 0 : (size_t)U_N * HD);
    const float* __restrict__ x_dst = isU ? xd_u : xd_i;
    const uint32_t* __restrict__ wpk = isU ? wpk_u : wpk_i;
    const float* __restrict__ bias = isU ? bias_u : bias_i;
    float* __restrict__ out = isU ? out_u : out_i;

    const int tid = threadIdx.x;
    const int lane = tid & 31;
    const int wid = tid >> 5;
    const int wm = wid & 3;
    const int wn = wid >> 2;
    const int row0 = bid * 128;
    const int g = lane >> 2;
    const int tig = lane & 3;

    float c[2][8][4];
#pragma unroll
    for (int mt = 0; mt < 2; mt++)
#pragma unroll
        for (int nt = 0; nt < 8; nt++)
#pragma unroll
            for (int q = 0; q < 4; q++) c[mt][nt][q] = 0.f;

#pragma unroll 1
    for (int kt = 0; kt < 8; kt++) {
        const bool isAgg = kt < 4;
        const int kbase = (kt & 3) * 32;
        const int kk2base = (kt & 3) * 16;
        const float* __restrict__ A = isAgg ? meanA : x_dst;
        const uint32_t* __restrict__ WB = wpk + (isAgg ? 0 : 16384);

        // A chunk (identical to r13): fp32 load + split + pack into [kk2][row]
#pragma unroll
        for (int rep = 0; rep < 4; rep++) {
            int fid = tid + rep * 256;     // 0..1023
            int r = fid >> 3;              // 0..127
            int c4 = fid & 7;              // float4 (4 k) index
            int grow = row0 + r;
            float4 v = make_float4(0.f, 0.f, 0.f, 0.f);
            if (grow < M)
                v = ((const float4*)(A + (size_t)grow * HD + kbase))[c4];
            float hx = bfr(v.x), hy = bfr(v.y), hz = bfr(v.z), hw = bfr(v.w);
            Ash[(c4 * 2 + 0) * PITCH + r] = pkbf(hx, hy);
            Ash[(c4 * 2 + 1) * PITCH + r] = pkbf(hz, hw);
            Asl[(c4 * 2 + 0) * PITCH + r] = pkbf(v.x - hx, v.y - hy);
            Asl[(c4 * 2 + 1) * PITCH + r] = pkbf(v.z - hz, v.w - hw);
        }
        // B chunk: pre-packed load, no cvt (same smem addresses as r13)
#pragma unroll
        for (int rep = 0; rep < 4; rep++) {
            int fid = tid + rep * 256;     // 0..1023
            bool isLo = fid >= 512;
            int f = fid & 511;
            int kk2 = f >> 5;              // 0..15
            int n4 = f & 31;               // 0..31
            const uint32_t* src = WB + (isLo ? 8192 : 0) + (kk2base + kk2) * 128;
            uint4 v = ((const uint4*)src)[n4];
            *(uint4*)&(isLo ? Bsl : Bsh)[kk2 * PITCH + n4 * 4] = v;
        }
        __syncthreads();

#pragma unroll
        for (int ks = 0; ks < 2; ks++) {
            const int arow = ks * 8;
            uint32_t ah[2][4], al[2][4];
#pragma unroll
            for (int mt = 0; mt < 2; mt++) {
                int m0 = wm * 32 + mt * 16;
                ah[mt][0] = Ash[(arow + tig) * PITCH + m0 + g];
                ah[mt][1] = Ash[(arow + tig) * PITCH + m0 + g + 8];
                ah[mt][2] = Ash[(arow + tig + 4) * PITCH + m0 + g];
                ah[mt][3] = Ash[(arow + tig + 4) * PITCH + m0 + g + 8];
                al[mt][0] = Asl[(arow + tig) * PITCH + m0 + g];
                al[mt][1] = Asl[(arow + tig) * PITCH + m0 + g + 8];
                al[mt][2] = Asl[(arow + tig + 4) * PITCH + m0 + g];
                al[mt][3] = Asl[(arow + tig + 4) * PITCH + m0 + g + 8];
            }
#pragma unroll
            for (int nt = 0; nt < 8; nt++) {
                int n0 = wn * 64 + nt * 8;
                uint32_t bh[2], bl[2];
                bh[0] = Bsh[(arow + tig) * PITCH + n0 + g];
                bh[1] = Bsh[(arow + tig + 4) * PITCH + n0 + g];
                bl[0] = Bsl[(arow + tig) * PITCH + n0 + g];
                bl[1] = Bsl[(arow + tig + 4) * PITCH + n0 + g];
                mma_bf16(c[0][nt], ah[0], bh);
                mma_bf16(c[1][nt], ah[1], bh);
                mma_bf16(c[0][nt], ah[0], bl);
                mma_bf16(c[1][nt], ah[1], bl);
                mma_bf16(c[0][nt], al[0], bh);
                mma_bf16(c[1][nt], al[1], bh);
            }
        }
        __syncthreads();
    }

    // epilogue (identical to r13)
#pragma unroll
    for (int mt = 0; mt < 2; mt++) {
        int r_lo = row0 + wm * 32 + mt * 16 + g;
        int r_hi = r_lo + 8;
#pragma unroll
        for (int nt = 0; nt < 8; nt++) {
            int col = wn * 64 + nt * 8 + tig * 2;
            float b0 = bias[col], b1 = bias[col + 1];
            float v0 = c[mt][nt][0] + b0;
            float v1 = c[mt][nt][1] + b1;
            float v2 = c[mt][nt][2] + b0;
            float v3 = c[mt][nt][3] + b1;
            if (RELU) {
                v0 = fmaxf(v0, 0.f); v1 = fmaxf(v1, 0.f);
                v2 = fmaxf(v2, 0.f); v3 = fmaxf(v3, 0.f);
            }
            if (r_lo < M) {
                *(float2*)(out + (size_t)r_lo * HD + col) = make_float2(v0, v1);
            }
            if (r_hi < M) {
                *(float2*)(out + (size_t)r_hi * HD + col) = make_float2(v2, v3);
            }
        }
    }
}

// ---------------- edge dot-product classifier ------------------------------
__global__ void classify_kernel(const float* __restrict__ u2, const float* __restrict__ i2,
                                const int* __restrict__ lbl, float* __restrict__ out) {
    int e = blockIdx.x * (blockDim.x >> 5) + (threadIdx.x >> 5);
    if (e >= EL_N) return;
    int lane = threadIdx.x & 31;
    int u  = lbl[e];
    int it = lbl[EL_N + e];
    float4 a = ((const float4*)(u2 + (size_t)u * HD))[lane];
    float4 b = ((const float4*)(i2 + (size_t)it * HD))[lane];
    float s = a.x * b.x + a.y * b.y + a.z * b.z + a.w * b.w;
#pragma unroll
    for (int o = 16; o > 0; o >>= 1) s += __shfl_xor_sync(0xFFFFFFFFu, s, o);
    if (lane == 0) out[e] = s;
}

// ---------------- cleanup: restore zero-state for next call -----------------
__global__ void cleanup_kernel(int* __restrict__ cnt,
                               unsigned long long* __restrict__ desc) {
    int i = blockIdx.x * blockDim.x + threadIdx.x;
    if (i < NPAD) cnt[i] = 0;
    if (i < NBLK) desc[i] = 0ull;
}

// ---------------- launch ----------------------------------------------------
extern "C" void kernel_launch(void* const* d_in, const int* in_sizes, int n_in,
                              void* d_out, int out_size) {
    const float* user_emb = (const float*)d_in[0];
    const float* item_emb = (const float*)d_in[1];
    const float* w1_ui_l = (const float*)d_in[2];
    const float* w1_ui_r = (const float*)d_in[3];
    const float* w1_iu_l = (const float*)d_in[4];
    const float* w1_iu_r = (const float*)d_in[5];
    const float* w2_ui_l = (const float*)d_in[6];
    const float* w2_ui_r = (const float*)d_in[7];
    const float* w2_iu_l = (const float*)d_in[8];
    const float* w2_iu_r = (const float*)d_in[9];
    const float* b1_ui = (const float*)d_in[10];
    const float* b1_iu = (const float*)d_in[11];
    const float* b2_ui = (const float*)d_in[12];
    const float* b2_iu = (const float*)d_in[13];
    const int* ei_ui = (const int*)d_in[16];
    const int* lbl   = (const int*)d_in[18];
    float* out = (float*)d_out;

    float *u1, *i1, *u2, *i2, *meanb;
    uint32_t* wpk;
    int *cnt, *cur, *off, *esrc_u, *esrc_i;
    unsigned long long* desc;
    cudaGetSymbolAddress((void**)&u1, g_u1);
    cudaGetSymbolAddress((void**)&i1, g_i1);
    cudaGetSymbolAddress((void**)&u2, g_u2);
    cudaGetSymbolAddress((void**)&i2, g_i2);
    cudaGetSymbolAddress((void**)&meanb, g_mean);
    cudaGetSymbolAddress((void**)&wpk, g_wpk);
    cudaGetSymbolAddress((void**)&cnt, g_cnt);
    cudaGetSymbolAddress((void**)&cur, g_cur);
    cudaGetSymbolAddress((void**)&off, g_off);
    cudaGetSymbolAddress((void**)&desc, g_desc);
    cudaGetSymbolAddress((void**)&esrc_u, g_esrc_u);
    cudaGetSymbolAddress((void**)&esrc_i, g_esrc_i);

    cudaFuncSetAttribute(sage_gemm_mma<true>,
                         cudaFuncAttributeMaxDynamicSharedMemorySize, GEMM_SMEM);
    cudaFuncSetAttribute(sage_gemm_mma<false>,
                         cudaFuncAttributeMaxDynamicSharedMemorySize, GEMM_SMEM);

    // ---- CSR build: 3 launches (cnt/desc pre-zeroed by prior cleanup) ----
    hist_kernel<<<(E_N + 255) / 256, 256>>>(ei_ui, cnt);            // 0
    scan_lookback<<<NBLK, 1024>>>(cnt, off, cur, desc);             // 1
    place_kernel<<<(E_N + 255) / 256, 256>>>(ei_ui, cur,
                                             esrc_u, esrc_i);       // 2

    const int MB = (N_TOT + 7) / 8;

    // ---- layer 1 ----
    mean_all<<<MB, 256>>>(off, esrc_u, esrc_i,
                          item_emb, user_emb, meanb);               // 3 (profiled)
    // weight order: 0=w1_iu_l 1=w1_iu_r 2=w1_ui_l 3=w1_ui_r 4..7=layer2
    wpack_kernel<<<8, 128>>>(w1_iu_l, w1_iu_r, w1_ui_l, w1_ui_r,
                             w2_iu_l, w2_iu_r, w2_ui_l, w2_ui_r, wpk); // 4
    sage_gemm_mma<true><<<UBK + IBK, 256, GEMM_SMEM>>>(meanb,
        user_emb, item_emb,
        wpk + 0 * 16384, wpk + 2 * 16384,
        b1_iu, b1_ui, u1, i1);                                      // 5

    // ---- layer 2 ----
    mean_all<<<MB, 256>>>(off, esrc_u, esrc_i, i1, u1, meanb);      // 6
    sage_gemm_mma<false><<<UBK + IBK, 256, GEMM_SMEM>>>(meanb,
        u1, i1,
        wpk + 4 * 16384, wpk + 6 * 16384,
        b2_iu, b2_ui, u2, i2);                                      // 7

    // ---- classifier ----
    classify_kernel<<<(EL_N + 7) / 8, 256>>>(u2, i2, lbl, out);     // 8

    // ---- restore zero-state for next call ----
    cleanup_kernel<<<(NPAD + 1023) / 1024, 1024>>>(cnt, desc);      // 9
}